// round 5
// baseline (speedup 1.0000x reference)
#include <cuda_runtime.h>
#include <cstdint>

// ============================================================================
// 16-qubit statevector simulator, 64 batches, 3 layers (Rot x16 + CNOT chain).
// Round 5: register-pressure cut -> 4 CTAs/SM (launch_bounds(256,4), <=64 regs).
//  * packed (re,im) f32x2 amplitudes, complex MAC via fma.rn.f32x2.
//  * CNOT chain = prefix-XOR permutation folded into addressing.
//  * passA: qubits 4..15 on tile bits [11:0]; passB: qubits 0..3 + relabel.
// ============================================================================

#define THREADS   256
#define TILE      4096
#define PAD_SLOTS (TILE + (TILE >> 4))   // 4352, slot = t + (t>>4)

typedef unsigned long long ull;

__device__ ull g_bufA[64 * 65536];
__device__ ull g_bufB[64 * 65536];

struct Smem {
    ull   amp[PAD_SLOTS];
    ull   um[16][8];
    float feats[16];
};
#define SMEM_BYTES ((int)sizeof(Smem))

// ---------------- packed f32x2 primitives ----------------
__device__ __forceinline__ ull f2fma(ull a, ull b, ull c) {
    ull d; asm("fma.rn.f32x2 %0, %1, %2, %3;" : "=l"(d) : "l"(a), "l"(b), "l"(c));
    return d;
}
__device__ __forceinline__ ull f2mul(ull a, ull b) {
    ull d; asm("mul.rn.f32x2 %0, %1, %2;" : "=l"(d) : "l"(a), "l"(b));
    return d;
}
__device__ __forceinline__ ull pk(float lo, float hi) {
    ull r; asm("mov.b64 %0, {%1, %2};" : "=l"(r) : "f"(lo), "f"(hi));
    return r;
}
__device__ __forceinline__ void upk(ull v, float& lo, float& hi) {
    asm("mov.b64 {%0, %1}, %2;" : "=f"(lo), "=f"(hi) : "l"(v));
}
__device__ __forceinline__ ull swp(ull v) {
    float lo, hi; upk(v, lo, hi); return pk(hi, lo);
}

// U = Rz(tz)@Ry(ty)@Rx(tx); per element u: c=(ur,ur), s=(-ui,ui);
// z = c*x + s*swap(x)
__device__ __forceinline__ void make_u(const float* __restrict__ vp, int layer, int q,
                                       ull* __restrict__ u8) {
    const float* p = vp + ((layer * 16) + q) * 6;
    float tx = p[0], ty = p[1], tz = p[2];
    float cx = cosf(0.5f * tx), sx = sinf(0.5f * tx);
    float cy = cosf(0.5f * ty), sy = sinf(0.5f * ty);
    float cz = cosf(0.5f * tz), sz = sinf(0.5f * tz);
    float m00r =  cy * cx, m00i =  sy * sx;
    float m01r = -sy * cx, m01i = -cy * sx;
    float m10r =  sy * cx, m10i = -cy * sx;
    float m11r =  cy * cx, m11i = -sy * sx;
    float u0 = cz * m00r + sz * m00i, u1 = cz * m00i - sz * m00r;
    float u2 = cz * m01r + sz * m01i, u3 = cz * m01i - sz * m01r;
    float u4 = cz * m10r - sz * m10i, u5 = cz * m10i + sz * m10r;
    float u6 = cz * m11r - sz * m11i, u7 = cz * m11i + sz * m11r;
    u8[0] = pk(u0, u0); u8[1] = pk(-u1, u1);
    u8[2] = pk(u2, u2); u8[3] = pk(-u3, u3);
    u8[4] = pk(u4, u4); u8[5] = pk(-u5, u5);
    u8[6] = pk(u6, u6); u8[7] = pk(-u7, u7);
}

__device__ __forceinline__ void cgate2(ull& a, ull& b,
                                       ull u0, ull u1, ull u2, ull u3,
                                       ull u4, ull u5, ull u6, ull u7) {
    ull na = f2fma(u0, a, f2fma(u1, swp(a), f2fma(u2, b, f2mul(u3, swp(b)))));
    ull nb = f2fma(u4, a, f2fma(u5, swp(a), f2fma(u6, b, f2mul(u7, swp(b)))));
    a = na; b = nb;
}

// ---------------------------------------------------------------------------
// Pass A: tile = index bits [11:0], tile id = bits [15:12] (16 tiles).
// permLoad applies prev layer CNOTs q=4..14: a = i ^ ((i>>1) & 0x7FF).
// Gates: lane bits 0..4 (qubits 15..11) via shfl; m1 reg bits 5..8
// (qubits 10..7); transpose; m2 reg bits 9..11 (qubits 6..4).
// m1: t = (w<<9)|(r<<5)|l    m2: t = (r<<8)|(l<<3)|w
// ---------------------------------------------------------------------------
__global__ void __launch_bounds__(THREADS, 4)
passA(const float* __restrict__ sr, const float* __restrict__ si,
      const ull* __restrict__ src, ull* __restrict__ dst,
      const float* __restrict__ vp, int layer, int permLoad, int fromInput) {
    extern __shared__ char smraw[];
    Smem* sm = (Smem*)smraw;
    int tid = threadIdx.x;
    int w = tid >> 5, l = tid & 31;
    int batch = blockIdx.x >> 4, tile = blockIdx.x & 15;
    int base  = batch << 16;
    int tbase = tile << 12;

    if (tid < 12) make_u(vp, layer, 15 - tid, sm->um[tid]);  // um[b]: gate on bit b
    __syncthreads();

    ull amp[16];

    if (fromInput) {
#pragma unroll
        for (int r = 0; r < 16; r++) {
            int i = base + (tbase | (w << 9) | (r << 5) | l);
            amp[r] = pk(sr[i], si[i]);
        }
    } else if (permLoad) {
#pragma unroll
        for (int r = 0; r < 16; r++) {
            int i = tbase | (w << 9) | (r << 5) | l;
            int a = i ^ ((i >> 1) & 0x7FF);   // inverse of CNOT chain q=4..14
            amp[r] = src[base + a];
        }
    } else {
#pragma unroll
        for (int r = 0; r < 16; r++)
            amp[r] = src[base + (tbase | (w << 9) | (r << 5) | l)];
    }

    // ---- gates on lane bits 0..4 (qubits 15..11) via shfl ----
    // load only the 4 side-selected coefficients (8 regs, not 16)
#pragma unroll
    for (int b = 0; b < 5; b++) {
        int side = (l >> b) & 1;
        ull cs = sm->um[b][side ? 6 : 0];
        ull ss = sm->um[b][side ? 7 : 1];
        ull cp = sm->um[b][side ? 4 : 2];
        ull sp = sm->um[b][side ? 5 : 3];
#pragma unroll
        for (int r = 0; r < 16; r++) {
            ull p = __shfl_xor_sync(0xffffffffu, amp[r], 1 << b);
            amp[r] = f2fma(cs, amp[r],
                     f2fma(ss, swp(amp[r]),
                     f2fma(cp, p, f2mul(sp, swp(p)))));
        }
    }

    // ---- gates on m1 register bits 5..8 (qubits 10..7) ----
#pragma unroll
    for (int b = 5; b < 9; b++) {
        ull u0 = sm->um[b][0], u1 = sm->um[b][1], u2 = sm->um[b][2], u3 = sm->um[b][3];
        ull u4 = sm->um[b][4], u5 = sm->um[b][5], u6 = sm->um[b][6], u7 = sm->um[b][7];
        int s = 1 << (b - 5);
#pragma unroll
        for (int r0 = 0; r0 < 16; r0++) {
            if (r0 & s) continue;
            cgate2(amp[r0], amp[r0 | s], u0, u1, u2, u3, u4, u5, u6, u7);
        }
    }

    // ---- transpose m1 -> m2 ----
#pragma unroll
    for (int r = 0; r < 16; r++) {
        int t = (w << 9) | (r << 5) | l;
        sm->amp[t + (t >> 4)] = amp[r];
    }
    __syncthreads();
#pragma unroll
    for (int r = 0; r < 16; r++) {
        int t = (r << 8) | (l << 3) | w;
        amp[r] = sm->amp[t + (t >> 4)];
    }

    // ---- gates on m2 register bits 9..11 (qubits 6..4) ----
#pragma unroll
    for (int b = 9; b < 12; b++) {
        ull u0 = sm->um[b][0], u1 = sm->um[b][1], u2 = sm->um[b][2], u3 = sm->um[b][3];
        ull u4 = sm->um[b][4], u5 = sm->um[b][5], u6 = sm->um[b][6], u7 = sm->um[b][7];
        int s = 1 << (b - 8);
#pragma unroll
        for (int r0 = 0; r0 < 16; r0++) {
            if (r0 & s) continue;
            cgate2(amp[r0], amp[r0 | s], u0, u1, u2, u3, u4, u5, u6, u7);
        }
    }

    // ---- transpose m2 -> m1, store ----
    __syncthreads();
#pragma unroll
    for (int r = 0; r < 16; r++) {
        int t = (r << 8) | (l << 3) | w;
        sm->amp[t + (t >> 4)] = amp[r];
    }
    __syncthreads();
#pragma unroll
    for (int r = 0; r < 16; r++) {
        int t = (w << 9) | (r << 5) | l;
        dst[base + (tbase | t)] = sm->amp[t + (t >> 4)];
    }
}

// ---------------------------------------------------------------------------
// Pass B: tile = global bits {15,14,13,12,11} + [6:0], tile id m = bits [10:7].
//   g = (t[11:7] << 11) | (m << 7) | t[6:0]
// Rotations on qubits 0..3 (g15..g12 = t11..t8 = m2 reg bits 3..0).
// !measure: CNOT q=0..3 relabel folded into smem write address, then store.
// measure: full-chain parity, Z expectations, linear head.
// ---------------------------------------------------------------------------
__global__ void __launch_bounds__(THREADS, 4)
passB(const ull* __restrict__ src, ull* __restrict__ dst,
      const float* __restrict__ vp, const float* __restrict__ hw,
      float* __restrict__ out, int layer, int measure) {
    extern __shared__ char smraw[];
    Smem* sm = (Smem*)smraw;
    int tid = threadIdx.x;
    int w = tid >> 5, l = tid & 31;
    int batch = blockIdx.x >> 4, m = blockIdx.x & 15;
    int base = batch << 16;

    if (tid < 4) make_u(vp, layer, tid, sm->um[tid]);  // um[q]: qubit q
    if (tid < 16) sm->feats[tid] = 0.0f;
    __syncthreads();

    ull amp[16];
#pragma unroll
    for (int r = 0; r < 16; r++) {
        int t = (w << 9) | (r << 5) | l;
        int g = ((t >> 7) << 11) | (m << 7) | (t & 0x7F);
        amp[r] = src[base + g];
    }

    // transpose m1 -> m2 (t[11:8] become register bits)
#pragma unroll
    for (int r = 0; r < 16; r++) {
        int t = (w << 9) | (r << 5) | l;
        sm->amp[t + (t >> 4)] = amp[r];
    }
    __syncthreads();
#pragma unroll
    for (int r = 0; r < 16; r++) {
        int t = (r << 8) | (l << 3) | w;
        amp[r] = sm->amp[t + (t >> 4)];
    }

    // rotations: qubit gq on g(15-gq) = t(11-gq) = reg bit (3-gq)
#pragma unroll
    for (int gq = 0; gq < 4; gq++) {
        ull u0 = sm->um[gq][0], u1 = sm->um[gq][1], u2 = sm->um[gq][2], u3 = sm->um[gq][3];
        ull u4 = sm->um[gq][4], u5 = sm->um[gq][5], u6 = sm->um[gq][6], u7 = sm->um[gq][7];
        int s = 8 >> gq;
#pragma unroll
        for (int r0 = 0; r0 < 16; r0++) {
            if (r0 & s) continue;
            cgate2(amp[r0], amp[r0 | s], u0, u1, u2, u3, u4, u5, u6, u7);
        }
    }

    if (!measure) {
        // CNOT q=0..3 relabel folded into smem write address:
        // r3'=r3, r2'=r2^r3', r1'=r1^r2', r0'=r0^r1', l4'=l4^r0'
        __syncthreads();
#pragma unroll
        for (int r = 0; r < 16; r++) {
            int b3 = (r >> 3) & 1;
            int b2 = ((r >> 2) & 1) ^ b3;
            int b1 = ((r >> 1) & 1) ^ b2;
            int b0 = (r & 1) ^ b1;
            int rn = (b3 << 3) | (b2 << 2) | (b1 << 1) | b0;
            int ln = l ^ (b0 << 4);
            int t = (rn << 8) | (ln << 3) | w;
            sm->amp[t + (t >> 4)] = amp[r];
        }
        __syncthreads();
#pragma unroll
        for (int r = 0; r < 16; r++) {
            int t = (w << 9) | (r << 5) | l;
            int g = ((t >> 7) << 11) | (m << 7) | (t & 0x7F);
            dst[base + g] = sm->amp[t + (t >> 4)];
        }
    } else {
        float acc[16];
#pragma unroll
        for (int q = 0; q < 16; q++) acc[q] = 0.0f;
#pragma unroll
        for (int r = 0; r < 16; r++) {
            int t = (r << 8) | (l << 3) | w;
            int j = ((t >> 7) << 11) | (m << 7) | (t & 0x7F);
            float re, im; upk(amp[r], re, im);
            float p = re * re + im * im;
            int f = j;                       // suffix-XOR parity
            f ^= f >> 1; f ^= f >> 2; f ^= f >> 4; f ^= f >> 8;
#pragma unroll
            for (int q = 0; q < 16; q++)
                acc[q] += ((f >> (15 - q)) & 1) ? -p : p;
        }
#pragma unroll
        for (int q = 0; q < 16; q++) {
#pragma unroll
            for (int off = 16; off; off >>= 1)
                acc[q] += __shfl_xor_sync(0xffffffffu, acc[q], off);
        }
        if (l == 0) {
#pragma unroll
            for (int q = 0; q < 16; q++) atomicAdd(&sm->feats[q], acc[q]);
        }
        __syncthreads();
        if (tid == 0) {
            float v = 0.0f;
            for (int q = 0; q < 16; q++) v += sm->feats[q] * hw[q];
            atomicAdd(&out[batch], v);
        }
    }
}

__global__ void initOut(float* __restrict__ out, const float* __restrict__ hb) {
    if (threadIdx.x < 64) out[threadIdx.x] = hb[0];
}

extern "C" void kernel_launch(void* const* d_in, const int* in_sizes, int n_in,
                              void* d_out, int out_size) {
    const float* sr = (const float*)d_in[0];
    const float* si = (const float*)d_in[1];
    const float* vp = (const float*)d_in[2];
    const float* hw = (const float*)d_in[3];
    const float* hb = (const float*)d_in[4];
    float* out = (float*)d_out;

    cudaFuncSetAttribute(passA, cudaFuncAttributeMaxDynamicSharedMemorySize, SMEM_BYTES);
    cudaFuncSetAttribute(passB, cudaFuncAttributeMaxDynamicSharedMemorySize, SMEM_BYTES);

    ull *b0, *b1;
    cudaGetSymbolAddress((void**)&b0, g_bufA);
    cudaGetSymbolAddress((void**)&b1, g_bufB);

    initOut<<<1, 64>>>(out, hb);
    // layer 0
    passA<<<1024, THREADS, SMEM_BYTES>>>(sr, si, nullptr, b0, vp, 0, 0, 1);
    passB<<<1024, THREADS, SMEM_BYTES>>>(b0, b1, vp, nullptr, nullptr, 0, 0);
    // layer 1 (load applies layer-0 CNOT chain q=4..14)
    passA<<<1024, THREADS, SMEM_BYTES>>>(nullptr, nullptr, b1, b0, vp, 1, 1, 0);
    passB<<<1024, THREADS, SMEM_BYTES>>>(b0, b1, vp, nullptr, nullptr, 1, 0);
    // layer 2
    passA<<<1024, THREADS, SMEM_BYTES>>>(nullptr, nullptr, b1, b0, vp, 2, 1, 0);
    passB<<<1024, THREADS, SMEM_BYTES>>>(b0, nullptr, vp, hw, out, 2, 1);
}

// round 6
// speedup vs baseline: 1.2927x; 1.2927x over previous
#include <cuda_runtime.h>
#include <cstdint>

// ============================================================================
// 16-qubit statevector simulator, 64 batches, 3 layers (Rot x16 + CNOT chain).
// Round 6: zero-shuffle design.
//  * passA (qubits 4..15, tile bits [11:0]): 3 register-bit gate groups
//    (r = t[11:8] -> t[3:0] -> t[7:4]) with 2 padded-smem transposes.
//  * passB (qubits 0..3): pure register kernel; load puts g[15:12] in reg
//    bits; CNOT q0..3 relabel folded into the STORE ADDRESS (suffix-XOR on
//    g[15:11]). No smem amps, no barriers.
//  * CNOT q=4..14 folded into next passA's load perm; full chain folded into
//    measurement parity on the final pass (separate kernel).
//  * packed (re,im) f32x2 amplitudes, complex MAC via fma.rn.f32x2.
// ============================================================================

#define THREADS   256
#define TILE      4096
#define PAD_SLOTS (TILE + (TILE >> 4))   // 4352, slot = t + (t>>4)

typedef unsigned long long ull;

__device__ ull g_bufA[64 * 65536];
__device__ ull g_bufB[64 * 65536];

struct Smem {
    ull amp[PAD_SLOTS];
    ull um[12][8];
};
#define SMEM_BYTES   ((int)sizeof(Smem))
struct SmemB {
    ull   um[4][8];
    float feats[16];
};
#define SMEMB_BYTES  ((int)sizeof(SmemB))

// ---------------- packed f32x2 primitives ----------------
__device__ __forceinline__ ull f2fma(ull a, ull b, ull c) {
    ull d; asm("fma.rn.f32x2 %0, %1, %2, %3;" : "=l"(d) : "l"(a), "l"(b), "l"(c));
    return d;
}
__device__ __forceinline__ ull f2mul(ull a, ull b) {
    ull d; asm("mul.rn.f32x2 %0, %1, %2;" : "=l"(d) : "l"(a), "l"(b));
    return d;
}
__device__ __forceinline__ ull pk(float lo, float hi) {
    ull r; asm("mov.b64 %0, {%1, %2};" : "=l"(r) : "f"(lo), "f"(hi));
    return r;
}
__device__ __forceinline__ void upk(ull v, float& lo, float& hi) {
    asm("mov.b64 {%0, %1}, %2;" : "=f"(lo), "=f"(hi) : "l"(v));
}
__device__ __forceinline__ ull swp(ull v) {
    float lo, hi; upk(v, lo, hi); return pk(hi, lo);
}

// U = Rz(tz)@Ry(ty)@Rx(tx); per element u: c=(ur,ur), s=(-ui,ui);
// z = c*x + s*swap(x)
__device__ __forceinline__ void make_u(const float* __restrict__ vp, int layer, int q,
                                       ull* __restrict__ u8) {
    const float* p = vp + ((layer * 16) + q) * 6;
    float tx = p[0], ty = p[1], tz = p[2];
    float cx = cosf(0.5f * tx), sx = sinf(0.5f * tx);
    float cy = cosf(0.5f * ty), sy = sinf(0.5f * ty);
    float cz = cosf(0.5f * tz), sz = sinf(0.5f * tz);
    float m00r =  cy * cx, m00i =  sy * sx;
    float m01r = -sy * cx, m01i = -cy * sx;
    float m10r =  sy * cx, m10i = -cy * sx;
    float m11r =  cy * cx, m11i = -sy * sx;
    float u0 = cz * m00r + sz * m00i, u1 = cz * m00i - sz * m00r;
    float u2 = cz * m01r + sz * m01i, u3 = cz * m01i - sz * m01r;
    float u4 = cz * m10r - sz * m10i, u5 = cz * m10i + sz * m10r;
    float u6 = cz * m11r - sz * m11i, u7 = cz * m11i + sz * m11r;
    u8[0] = pk(u0, u0); u8[1] = pk(-u1, u1);
    u8[2] = pk(u2, u2); u8[3] = pk(-u3, u3);
    u8[4] = pk(u4, u4); u8[5] = pk(-u5, u5);
    u8[6] = pk(u6, u6); u8[7] = pk(-u7, u7);
}

__device__ __forceinline__ void cgate2(ull& a, ull& b, const ull* __restrict__ u) {
    ull u0 = u[0], u1 = u[1], u2 = u[2], u3 = u[3];
    ull u4 = u[4], u5 = u[5], u6 = u[6], u7 = u[7];
    ull na = f2fma(u0, a, f2fma(u1, swp(a), f2fma(u2, b, f2mul(u3, swp(b)))));
    ull nb = f2fma(u4, a, f2fma(u5, swp(a), f2fma(u6, b, f2mul(u7, swp(b)))));
    a = na; b = nb;
}

// apply gates um[b0+k] on register bit k, k=0..3
__device__ __forceinline__ void gate4(ull* __restrict__ amp,
                                      const ull (* __restrict__ um)[8], int b0) {
#pragma unroll
    for (int k = 0; k < 4; k++) {
        int s = 1 << k;
#pragma unroll
        for (int r0 = 0; r0 < 16; r0++) {
            if (r0 & s) continue;
            cgate2(amp[r0], amp[r0 | s], um[b0 + k]);
        }
    }
}

// ---------------------------------------------------------------------------
// Pass A: tile = index bits [11:0], tile id = bits [15:12] (16 tiles/batch).
// permLoad applies prev-layer CNOTs q=4..14: a = i ^ ((i>>1) & 0x7FF).
// m1: t = (r<<8)|tid  (reg bits t[11:8] -> qubits 4..7,  um[8..11])
// m2: t = (tid<<4)|r  (reg bits t[3:0]  -> qubits 15..12, um[0..3])
// m3: t = (tid>>4<<8)|(r<<4)|(tid&15) (reg bits t[7:4] -> qubits 8..11, um[4..7])
// um[b] = gate for tile bit b = qubit 15-b.
// Loads (m1) and stores (m3) are both coalesced; only 2 smem transposes.
// ---------------------------------------------------------------------------
__global__ void __launch_bounds__(THREADS, 4)
passA(const float* __restrict__ sr, const float* __restrict__ si,
      const ull* __restrict__ src, ull* __restrict__ dst,
      const float* __restrict__ vp, int layer, int permLoad, int fromInput) {
    extern __shared__ char smraw[];
    Smem* sm = (Smem*)smraw;
    int tid = threadIdx.x;
    int batch = blockIdx.x >> 4, tile = blockIdx.x & 15;
    int base  = batch << 16;
    int tbase = tile << 12;

    if (tid < 12) make_u(vp, layer, 15 - tid, sm->um[tid]);
    __syncthreads();

    ull amp[16];

    // ---- load in m1 ----
    if (fromInput) {
#pragma unroll
        for (int r = 0; r < 16; r++) {
            int i = base + (tbase | (r << 8) | tid);
            amp[r] = pk(sr[i], si[i]);
        }
    } else if (permLoad) {
#pragma unroll
        for (int r = 0; r < 16; r++) {
            int i = tbase | (r << 8) | tid;
            int a = i ^ ((i >> 1) & 0x7FF);   // inverse of CNOT chain q=4..14
            amp[r] = src[base + a];
        }
    } else {
#pragma unroll
        for (int r = 0; r < 16; r++)
            amp[r] = src[base + (tbase | (r << 8) | tid)];
    }

    // ---- gates on m1 reg bits t[11:8] (qubits 7..4) ----
    gate4(amp, sm->um, 8);

    // ---- transpose m1 -> m2 ----
#pragma unroll
    for (int r = 0; r < 16; r++) {
        int t = (r << 8) | tid;
        sm->amp[t + (t >> 4)] = amp[r];
    }
    __syncthreads();
#pragma unroll
    for (int r = 0; r < 16; r++) {
        int t = (tid << 4) | r;
        amp[r] = sm->amp[t + (t >> 4)];
    }

    // ---- gates on m2 reg bits t[3:0] (qubits 15..12) ----
    gate4(amp, sm->um, 0);

    // ---- transpose m2 -> m3 ----
    __syncthreads();
#pragma unroll
    for (int r = 0; r < 16; r++) {
        int t = (tid << 4) | r;
        sm->amp[t + (t >> 4)] = amp[r];
    }
    __syncthreads();
#pragma unroll
    for (int r = 0; r < 16; r++) {
        int t = ((tid >> 4) << 8) | (r << 4) | (tid & 15);
        amp[r] = sm->amp[t + (t >> 4)];
    }

    // ---- gates on m3 reg bits t[7:4] (qubits 11..8) ----
    gate4(amp, sm->um, 4);

    // ---- store directly from m3 ----
#pragma unroll
    for (int r = 0; r < 16; r++) {
        int t = ((tid >> 4) << 8) | (r << 4) | (tid & 15);
        dst[base + (tbase | t)] = amp[r];
    }
}

// ---------------------------------------------------------------------------
// Pass B (store variant): tile id m = bits g[10:7].
//   t = (r<<8)|tid,  g = (t[11:7] << 11) | (m << 7) | t[6:0]
// Reg bits r[3:0] = g[15:12] = qubits 3..0  ->  4 gate levels in registers.
// CNOT q=0..3 relabel = suffix-XOR on g[15:11], folded into store address.
// ---------------------------------------------------------------------------
__global__ void __launch_bounds__(THREADS, 4)
passB(const ull* __restrict__ src, ull* __restrict__ dst,
      const float* __restrict__ vp, int layer) {
    __shared__ SmemB sm;
    int tid = threadIdx.x;
    int batch = blockIdx.x >> 4, m = blockIdx.x & 15;
    int base = batch << 16;

    if (tid < 4) make_u(vp, layer, 3 - tid, sm.um[tid]);  // um[k]: qubit 3-k (reg bit k)
    __syncthreads();

    ull amp[16];
#pragma unroll
    for (int r = 0; r < 16; r++) {
        int t = (r << 8) | tid;
        int g = ((t >> 7) << 11) | (m << 7) | (t & 0x7F);
        amp[r] = src[base + g];
    }

    // gates: reg bit k = g[12+k] = qubit 3-k
    gate4(amp, sm.um, 0);

    // store with CNOT q=0..3 relabel: suffix-XOR on h = g[15:11]
#pragma unroll
    for (int r = 0; r < 16; r++) {
        int t = (r << 8) | tid;
        int h = t >> 7;                     // 5 bits = g[15:11]
        h ^= h >> 1; h ^= h >> 2; h ^= h >> 4;
        int gp = (h << 11) | (m << 7) | (t & 0x7F);
        dst[base + gp] = amp[r];
    }
}

// ---------------------------------------------------------------------------
// Pass B (measure variant): gates on qubits 0..3, then fold the ENTIRE final
// CNOT chain into the parity (final bit k = parity(j >> k)), reduce Z
// expectations, apply linear head.
// ---------------------------------------------------------------------------
__global__ void __launch_bounds__(THREADS, 4)
passBmeas(const ull* __restrict__ src, const float* __restrict__ vp,
          const float* __restrict__ hw, float* __restrict__ out, int layer) {
    __shared__ SmemB sm;
    int tid = threadIdx.x;
    int l = tid & 31;
    int batch = blockIdx.x >> 4, m = blockIdx.x & 15;
    int base = batch << 16;

    if (tid < 4) make_u(vp, layer, 3 - tid, sm.um[tid]);
    if (tid < 16) sm.feats[tid] = 0.0f;
    __syncthreads();

    ull amp[16];
#pragma unroll
    for (int r = 0; r < 16; r++) {
        int t = (r << 8) | tid;
        int g = ((t >> 7) << 11) | (m << 7) | (t & 0x7F);
        amp[r] = src[base + g];
    }

    gate4(amp, sm.um, 0);

    float acc[16];
#pragma unroll
    for (int q = 0; q < 16; q++) acc[q] = 0.0f;
#pragma unroll
    for (int r = 0; r < 16; r++) {
        int t = (r << 8) | tid;
        int j = ((t >> 7) << 11) | (m << 7) | (t & 0x7F);
        float re, im; upk(amp[r], re, im);
        float p = re * re + im * im;
        int f = j;                           // suffix-XOR parity
        f ^= f >> 1; f ^= f >> 2; f ^= f >> 4; f ^= f >> 8;
#pragma unroll
        for (int q = 0; q < 16; q++)
            acc[q] += ((f >> (15 - q)) & 1) ? -p : p;
    }
#pragma unroll
    for (int q = 0; q < 16; q++) {
#pragma unroll
        for (int off = 16; off; off >>= 1)
            acc[q] += __shfl_xor_sync(0xffffffffu, acc[q], off);
    }
    if (l == 0) {
#pragma unroll
        for (int q = 0; q < 16; q++) atomicAdd(&sm.feats[q], acc[q]);
    }
    __syncthreads();
    if (tid == 0) {
        float v = 0.0f;
        for (int q = 0; q < 16; q++) v += sm.feats[q] * hw[q];
        atomicAdd(&out[batch], v);
    }
}

__global__ void initOut(float* __restrict__ out, const float* __restrict__ hb) {
    if (threadIdx.x < 64) out[threadIdx.x] = hb[0];
}

extern "C" void kernel_launch(void* const* d_in, const int* in_sizes, int n_in,
                              void* d_out, int out_size) {
    const float* sr = (const float*)d_in[0];
    const float* si = (const float*)d_in[1];
    const float* vp = (const float*)d_in[2];
    const float* hw = (const float*)d_in[3];
    const float* hb = (const float*)d_in[4];
    float* out = (float*)d_out;

    cudaFuncSetAttribute(passA, cudaFuncAttributeMaxDynamicSharedMemorySize, SMEM_BYTES);

    ull *b0, *b1;
    cudaGetSymbolAddress((void**)&b0, g_bufA);
    cudaGetSymbolAddress((void**)&b1, g_bufB);

    initOut<<<1, 64>>>(out, hb);
    // layer 0
    passA<<<1024, THREADS, SMEM_BYTES>>>(sr, si, nullptr, b0, vp, 0, 0, 1);
    passB<<<1024, THREADS>>>(b0, b1, vp, 0);
    // layer 1 (load applies layer-0 CNOT chain q=4..14)
    passA<<<1024, THREADS, SMEM_BYTES>>>(nullptr, nullptr, b1, b0, vp, 1, 1, 0);
    passB<<<1024, THREADS>>>(b0, b1, vp, 1);
    // layer 2
    passA<<<1024, THREADS, SMEM_BYTES>>>(nullptr, nullptr, b1, b0, vp, 2, 1, 0);
    passBmeas<<<1024, THREADS>>>(b0, vp, hw, out, 2);
}